// round 1
// baseline (speedup 1.0000x reference)
#include <cuda_runtime.h>
#include <cuda_bf16.h>

#define PP   4096
#define TT   128
#define AA   32
#define KSEL 409
#define INF_F 1e30f
#define TEMP_F 0.5f

__device__ float g_dists[PP];
__device__ float g_w[PP];
__device__ float g_ssum;

// ---------------------------------------------------------------------------
// Kernel 1: DTW min-plus DP. One warp per p; 4 columns per lane; row-wise
// (min,+) first-order recurrence solved with a warp inclusive scan over
// transform pairs (a,b) : x -> min(b, x + a).
// ---------------------------------------------------------------------------
__global__ void __launch_bounds__(256) dtw_kernel(const float* __restrict__ obs) {
    int warp = (blockIdx.x * blockDim.x + threadIdx.x) >> 5;
    int lane = threadIdx.x & 31;
    const float4* row = (const float4*)obs + (size_t)warp * (TT * TT / 4);

    float pd0 = INF_F, pd1 = INF_F, pd2 = INF_F, pd3 = INF_F;  // D_{i-1} for this lane's 4 cols
    float B = 0.0f;                                            // Dprev[-1] boundary (0 for row 0, INF after)

    float4 c = row[lane];  // prefetch row 0
    for (int i = 0; i < TT; ++i) {
        int nx = (i < TT - 1) ? (i + 1) : i;
        float4 cn = row[nx * 32 + lane];  // prefetch next row (overlaps scan latency)

        float lp = __shfl_up_sync(0xffffffffu, pd3, 1);  // Dprev[j-1] for this lane's col 0
        if (lane == 0) lp = B;

        float e0 = fminf(pd0, lp)  + c.x;
        float e1 = fminf(pd1, pd0) + c.y;
        float e2 = fminf(pd2, pd1) + c.z;
        float e3 = fminf(pd3, pd2) + c.w;

        // local compose of the lane's 4 transforms
        float a = c.x + c.y + c.z + c.w;
        float b = e0;
        b = fminf(e1, b + c.y);
        b = fminf(e2, b + c.z);
        b = fminf(e3, b + c.w);

        // warp inclusive scan: (aL,bL) (+) (aR,bR) = (aL+aR, min(bR, bL+aR))
        #pragma unroll
        for (int d = 1; d < 32; d <<= 1) {
            float ao = __shfl_up_sync(0xffffffffu, a, d);
            float bo = __shfl_up_sync(0xffffffffu, b, d);
            if (lane >= d) { b = fminf(b, bo + a); a += ao; }
        }

        float xin = __shfl_up_sync(0xffffffffu, b, 1);  // D[i, 4*lane - 1]
        if (lane == 0) xin = INF_F;

        pd0 = fminf(e0, xin + c.x);
        pd1 = fminf(e1, pd0 + c.y);
        pd2 = fminf(e2, pd1 + c.z);
        pd3 = fminf(e3, pd2 + c.w);

        B = INF_F;
        c = cn;
    }
    if (lane == 31) g_dists[warp] = pd3;
}

// ---------------------------------------------------------------------------
// Kernel 2: single-block exact top-K selection + weight computation.
// Radix-select the K-th smallest (exact float bits), index-ordered tie ranks
// (matches lax.top_k tie-breaking), then normalized exp weights.
// All reductions are fixed-order shfl trees (deterministic).
// ---------------------------------------------------------------------------
__global__ void __launch_bounds__(1024) select_kernel() {
    __shared__ unsigned sh_u[PP];
    __shared__ unsigned hist[256];
    __shared__ float fred[32];
    __shared__ int   ired[32];
    __shared__ float s_min, s_Se;
    __shared__ int s_cnt_lt;
    __shared__ unsigned s_prefix;
    __shared__ int s_krem;

    int tid = threadIdx.x, lane = tid & 31, wid = tid >> 5;

    float d[4]; unsigned u[4];
    float lmin = INF_F;
    #pragma unroll
    for (int e = 0; e < 4; ++e) {
        float x = g_dists[tid * 4 + e];
        d[e] = x;
        unsigned b = __float_as_uint(x);
        unsigned m = (b & 0x80000000u) ? 0xFFFFFFFFu : 0x80000000u;  // order-preserving transform
        u[e] = b ^ m;
        sh_u[tid * 4 + e] = u[e];
        lmin = fminf(lmin, x);
    }
    if (tid == 0) { s_cnt_lt = 0; s_prefix = 0; s_krem = KSEL; }

    // block min
    #pragma unroll
    for (int o = 16; o; o >>= 1) lmin = fminf(lmin, __shfl_xor_sync(0xffffffffu, lmin, o));
    if (lane == 0) fred[wid] = lmin;
    __syncthreads();
    if (wid == 0) {
        float v = fred[lane];
        #pragma unroll
        for (int o = 16; o; o >>= 1) v = fminf(v, __shfl_xor_sync(0xffffffffu, v, o));
        if (lane == 0) s_min = v;
    }
    __syncthreads();

    // 4-pass radix select (MSB -> LSB) of the K-th smallest bit pattern
    for (int shift = 24; shift >= 0; shift -= 8) {
        if (tid < 256) hist[tid] = 0;
        __syncthreads();
        unsigned pref  = s_prefix;
        unsigned hmask = (shift == 24) ? 0u : (0xFFFFFFFFu << (shift + 8));
        #pragma unroll
        for (int e = 0; e < 4; ++e)
            if ((u[e] & hmask) == pref) atomicAdd(&hist[(u[e] >> shift) & 255], 1u);
        __syncthreads();
        if (tid == 0) {
            unsigned krem = (unsigned)s_krem, cum = 0; int dd = 0;
            for (; dd < 256; ++dd) {
                unsigned h = hist[dd];
                if (cum + h >= krem) { s_krem = (int)(krem - cum); break; }
                cum += h;
            }
            s_prefix = pref | ((unsigned)dd << shift);
        }
        __syncthreads();
    }
    unsigned tau = s_prefix;

    // count(u < tau) and index-ordered rank among ties
    int clt = 0, tc = 0;
    #pragma unroll
    for (int e = 0; e < 4; ++e) { clt += (u[e] < tau); tc += (u[e] == tau); }
    atomicAdd(&s_cnt_lt, clt);

    int incl = tc;
    #pragma unroll
    for (int o = 1; o < 32; o <<= 1) { int v = __shfl_up_sync(0xffffffffu, incl, o); if (lane >= o) incl += v; }
    if (lane == 31) ired[wid] = incl;
    __syncthreads();
    if (wid == 0) {
        int v = ired[lane], s = v;
        #pragma unroll
        for (int o = 1; o < 32; o <<= 1) { int w2 = __shfl_up_sync(0xffffffffu, s, o); if (lane >= o) s += w2; }
        ired[lane] = s - v;  // exclusive warp offsets
    }
    __syncthreads();

    int trank = ired[wid] + (incl - tc);
    int need  = KSEL - s_cnt_lt;
    float mind = s_min;

    float ws[4]; float esum = 0.f;
    #pragma unroll
    for (int e = 0; e < 4; ++e) {
        bool sel = (u[e] < tau);
        if (u[e] == tau) { sel = (trank < need); trank++; }
        float w = sel ? expf(TEMP_F * (mind - d[e])) : 0.f;
        ws[e] = w; esum += w;
    }

    // Se = sum of unnormalized weights
    float se = esum;
    #pragma unroll
    for (int o = 16; o; o >>= 1) se += __shfl_xor_sync(0xffffffffu, se, o);
    if (lane == 0) fred[wid] = se;
    __syncthreads();
    if (wid == 0) {
        float v = fred[lane];
        #pragma unroll
        for (int o = 16; o; o >>= 1) v += __shfl_xor_sync(0xffffffffu, v, o);
        if (lane == 0) s_Se = v;
    }
    __syncthreads();
    float Se = s_Se;

    // normalized scores + ssum (matches reference's score/score.sum(); ssum = score.sum())
    float ssl = 0.f;
    #pragma unroll
    for (int e = 0; e < 4; ++e) {
        float sc = ws[e] / Se;
        g_w[tid * 4 + e] = sc;
        ssl += sc;
    }
    __syncthreads();
    #pragma unroll
    for (int o = 16; o; o >>= 1) ssl += __shfl_xor_sync(0xffffffffu, ssl, o);
    if (lane == 0) fred[wid] = ssl;
    __syncthreads();
    if (wid == 0) {
        float v = fred[lane];
        #pragma unroll
        for (int o = 16; o; o >>= 1) v += __shfl_xor_sync(0xffffffffu, v, o);
        if (lane == 0) g_ssum = v;
    }
}

// ---------------------------------------------------------------------------
// Kernel 3: weighted mean/std over elite actions. One block per t, lane = a.
// Warp-uniform skip of non-elite p -> only elite noise rows are loaded.
// ---------------------------------------------------------------------------
__global__ void __launch_bounds__(256) reduce_kernel(const float* __restrict__ means,
                                                     const float* __restrict__ stds,
                                                     const float* __restrict__ noise,
                                                     float* __restrict__ out) {
    __shared__ float s1s[8][AA];
    __shared__ float s2s[8][AA];
    int t  = blockIdx.x;
    int a  = threadIdx.x & 31;
    int wg = threadIdx.x >> 5;  // 8 warps

    float mn = means[t * AA + a];
    float sd = stds[t * AA + a];
    const float* np = noise + (size_t)t * PP * AA;

    float s1 = 0.f, s2 = 0.f;
    for (int p = wg; p < PP; p += 8) {
        float w = g_w[p];          // broadcast; identical across the warp
        if (w != 0.f) {            // warp-uniform branch
            float x = mn + sd * np[(size_t)p * AA + a];
            x = fminf(fmaxf(x, -1.f), 1.f);
            s1 += w * x;
            s2 += w * x * x;
        }
    }
    s1s[wg][a] = s1; s2s[wg][a] = s2;
    __syncthreads();

    if (wg == 0) {
        float S1 = 0.f, S2 = 0.f;
        #pragma unroll
        for (int k = 0; k < 8; ++k) { S1 += s1s[k][a]; S2 += s2s[k][a]; }
        float ssum  = g_ssum;
        float denom = ssum + 1e-9f;
        float m   = S1 / denom;
        float var = (S2 - 2.f * m * S1 + m * m * ssum) / denom;
        var = fmaxf(var, 0.f);
        float st = sqrtf(var);
        st = fminf(fmaxf(st, 0.05f), 1.0f);
        out[t * AA + a]           = 0.1f * mn + 0.9f * m;   // MOM*means + (1-MOM)*_mean
        out[TT * AA + t * AA + a] = st;
    }
}

extern "C" void kernel_launch(void* const* d_in, const int* in_sizes, int n_in,
                              void* d_out, int out_size) {
    const float* obs   = (const float*)d_in[0];  // [P, T, T]
    const float* means = (const float*)d_in[1];  // [T, 1, A]
    const float* stds  = (const float*)d_in[2];  // [T, 1, A]
    const float* noise = (const float*)d_in[3];  // [T, P, A]
    float* out = (float*)d_out;                  // [2, T, 1, A]

    dtw_kernel<<<PP / 8, 256>>>(obs);            // 4096 warps, one per p
    select_kernel<<<1, 1024>>>();
    reduce_kernel<<<TT, 256>>>(means, stds, noise, out);
}

// round 2
// speedup vs baseline: 2.2909x; 2.2909x over previous
#include <cuda_runtime.h>
#include <cuda_bf16.h>

#define PP   4096
#define TT   128
#define AA   32
#define KSEL 409
#define INF_F 1e30f
#define TEMP_F 0.5f

__device__ float    g_dists[PP];
__device__ int      g_eidx[KSEL];
__device__ float    g_ew[KSEL];
__device__ float    g_ssum;

// ---------------------------------------------------------------------------
// Kernel 1: DTW min-plus DP. One warp per p, 4 cols/lane.
// Row solve: D_j = S_j + prefmin_{k<=j}(e_k - S_k), S = prefix sums of costs.
// The S-scan of the NEXT row is DP-independent -> overlaps the min-scan chain.
// ---------------------------------------------------------------------------
__device__ __forceinline__ void sum_scan(float4 c, int lane,
                                         float& S0, float& S1, float& S2, float& S3) {
    float s0 = c.x, s1 = s0 + c.y, s2 = s1 + c.z, s3 = s2 + c.w;
    float t = s3;
    #pragma unroll
    for (int d = 1; d < 32; d <<= 1) {
        float o = __shfl_up_sync(0xffffffffu, t, d);
        if (lane >= d) t += o;
    }
    float ex = t - s3;
    S0 = ex + s0; S1 = ex + s1; S2 = ex + s2; S3 = t;
}

__global__ void __launch_bounds__(256) dtw_kernel(const float* __restrict__ obs) {
    int warp = (blockIdx.x * blockDim.x + threadIdx.x) >> 5;
    int lane = threadIdx.x & 31;
    const float4* row = (const float4*)obs + (size_t)warp * (TT * TT / 4);

    float4 c  = row[lane];       // row 0
    float4 cn = row[32 + lane];  // row 1
    float S0, S1, S2, S3;
    sum_scan(c, lane, S0, S1, S2, S3);

    float pd0 = INF_F, pd1 = INF_F, pd2 = INF_F, pd3 = INF_F;
    float B = 0.0f;  // Dprev[-1]: 0 for first row, INF after

    for (int i = 0; i < TT; ++i) {
        int nx = (i + 2 < TT) ? (i + 2) : (TT - 1);
        float4 c2 = row[nx * 32 + lane];  // prefetch depth 2

        float lp = __shfl_up_sync(0xffffffffu, pd3, 1);
        if (lane == 0) lp = B;

        float e0 = fminf(pd0, lp)  + c.x;
        float e1 = fminf(pd1, pd0) + c.y;
        float e2 = fminf(pd2, pd1) + c.z;
        float e3 = fminf(pd3, pd2) + c.w;

        // local inclusive prefix-min of m_j = e_j - S_j
        float l0 = e0 - S0;
        float l1 = fminf(l0, e1 - S1);
        float l2 = fminf(l1, e2 - S2);
        float l3 = fminf(l2, e3 - S3);

        // warp inclusive min-scan (unpredicated: shfl_up OOR returns own value)
        float g = l3;
        #pragma unroll
        for (int d = 1; d < 32; d <<= 1)
            g = fminf(g, __shfl_up_sync(0xffffffffu, g, d));

        float ex = __shfl_up_sync(0xffffffffu, g, 1);  // exclusive carry
        if (lane == 0) ex = INF_F;

        pd0 = S0 + fminf(ex, l0);
        pd1 = S1 + fminf(ex, l1);
        pd2 = S2 + fminf(ex, l2);
        pd3 = S3 + fminf(ex, l3);

        // next row's S (independent of DP chain -> fills scan stalls)
        sum_scan(cn, lane, S0, S1, S2, S3);

        c = cn; cn = c2; B = INF_F;
    }
    if (lane == 31) g_dists[warp] = pd3;
}

// ---------------------------------------------------------------------------
// Kernel 2: single-block exact radix top-K + weights + elite compaction.
// All cross-thread steps parallelized (no serial 256-bin walks).
// ---------------------------------------------------------------------------
__global__ void __launch_bounds__(1024) select_kernel() {
    __shared__ unsigned hist[256];
    __shared__ unsigned wsum[32];
    __shared__ float    fred[32];
    __shared__ int      ired[32];
    __shared__ int      pofs[32];
    __shared__ float    s_min, s_Se;
    __shared__ unsigned s_prefix;
    __shared__ int      s_krem, s_cnt_lt;

    int tid = threadIdx.x, lane = tid & 31, wid = tid >> 5;

    float d[4]; unsigned u[4];
    float lmin = INF_F;
    #pragma unroll
    for (int e = 0; e < 4; ++e) {
        float x = g_dists[tid * 4 + e];
        d[e] = x;
        unsigned b = __float_as_uint(x);
        u[e] = b ^ ((b & 0x80000000u) ? 0xFFFFFFFFu : 0x80000000u);
        lmin = fminf(lmin, x);
    }
    if (tid == 0) { s_prefix = 0; s_krem = KSEL; s_cnt_lt = 0; }

    // block min
    #pragma unroll
    for (int o = 16; o; o >>= 1) lmin = fminf(lmin, __shfl_xor_sync(0xffffffffu, lmin, o));
    if (lane == 0) fred[wid] = lmin;
    __syncthreads();
    if (wid == 0) {
        float v = fred[lane];
        #pragma unroll
        for (int o = 16; o; o >>= 1) v = fminf(v, __shfl_xor_sync(0xffffffffu, v, o));
        if (lane == 0) s_min = v;
    }
    __syncthreads();

    // 4-pass radix select, parallel digit scan
    for (int shift = 24; shift >= 0; shift -= 8) {
        if (tid < 256) hist[tid] = 0;
        __syncthreads();
        unsigned pref  = s_prefix;
        int      krem  = s_krem;
        unsigned hmask = (shift == 24) ? 0u : (0xFFFFFFFFu << (shift + 8));
        #pragma unroll
        for (int e = 0; e < 4; ++e)
            if ((u[e] & hmask) == pref) atomicAdd(&hist[(u[e] >> shift) & 255], 1u);
        __syncthreads();
        unsigned v = 0, inc = 0;
        if (tid < 256) {
            v = hist[tid];
            inc = v;
            #pragma unroll
            for (int o = 1; o < 32; o <<= 1) {
                unsigned x = __shfl_up_sync(0xffffffffu, inc, o);
                if (lane >= o) inc += x;
            }
            if (lane == 31) wsum[wid] = inc;
        }
        __syncthreads();
        if (tid < 256) {
            unsigned off = 0;
            #pragma unroll
            for (int k = 0; k < 8; ++k) off += (k < wid) ? wsum[k] : 0u;
            unsigned cum  = off + inc;     // inclusive
            unsigned prev = cum - v;       // exclusive
            if (prev < (unsigned)krem && (unsigned)krem <= cum) {
                s_prefix = pref | ((unsigned)tid << shift);
                s_krem   = krem - (int)prev;
            }
        }
        __syncthreads();
    }
    unsigned tau = s_prefix;

    // count(u < tau), index-ordered tie ranks
    int clt = 0, tc = 0;
    #pragma unroll
    for (int e = 0; e < 4; ++e) { clt += (u[e] < tau); tc += (u[e] == tau); }
    atomicAdd(&s_cnt_lt, clt);

    int incl = tc;
    #pragma unroll
    for (int o = 1; o < 32; o <<= 1) { int v = __shfl_up_sync(0xffffffffu, incl, o); if (lane >= o) incl += v; }
    if (lane == 31) ired[wid] = incl;
    __syncthreads();
    if (wid == 0) {
        int v = ired[lane], s = v;
        #pragma unroll
        for (int o = 1; o < 32; o <<= 1) { int w2 = __shfl_up_sync(0xffffffffu, s, o); if (lane >= o) s += w2; }
        ired[lane] = s - v;  // exclusive warp offset for tie counts
    }
    __syncthreads();

    int trank = ired[wid] + (incl - tc);
    int need  = KSEL - s_cnt_lt;
    float mind = s_min;

    bool  sel[4]; float ws[4]; float esum = 0.f; int nsel = 0;
    #pragma unroll
    for (int e = 0; e < 4; ++e) {
        bool s = (u[e] < tau);
        if (u[e] == tau) { s = (trank < need); trank++; }
        sel[e] = s;
        float w = s ? expf(TEMP_F * (mind - d[e])) : 0.f;
        ws[e] = w; esum += w; nsel += s;
    }

    // Se = sum of raw weights (deterministic tree)
    float se = esum;
    #pragma unroll
    for (int o = 16; o; o >>= 1) se += __shfl_xor_sync(0xffffffffu, se, o);
    if (lane == 0) fred[wid] = se;
    __syncthreads();
    if (wid == 0) {
        float v = fred[lane];
        #pragma unroll
        for (int o = 16; o; o >>= 1) v += __shfl_xor_sync(0xffffffffu, v, o);
        if (lane == 0) s_Se = v;
    }
    __syncthreads();
    float Se = s_Se;

    // compaction offsets: exclusive scan of per-thread nsel
    int pincl = nsel;
    #pragma unroll
    for (int o = 1; o < 32; o <<= 1) { int v = __shfl_up_sync(0xffffffffu, pincl, o); if (lane >= o) pincl += v; }
    if (lane == 31) pofs[wid] = pincl;
    __syncthreads();
    if (wid == 0) {
        int v = pofs[lane], s = v;
        #pragma unroll
        for (int o = 1; o < 32; o <<= 1) { int w2 = __shfl_up_sync(0xffffffffu, s, o); if (lane >= o) s += w2; }
        pofs[lane] = s - v;
    }
    __syncthreads();
    int pos = pofs[wid] + (pincl - nsel);

    float ssl = 0.f;
    #pragma unroll
    for (int e = 0; e < 4; ++e) {
        if (sel[e]) {
            float sc = ws[e] / Se;
            g_eidx[pos] = tid * 4 + e;
            g_ew[pos]   = sc;
            pos++;
            ssl += sc;
        }
    }

    // ssum = sum of normalized scores
    #pragma unroll
    for (int o = 16; o; o >>= 1) ssl += __shfl_xor_sync(0xffffffffu, ssl, o);
    if (lane == 0) fred[wid] = ssl;
    __syncthreads();
    if (wid == 0) {
        float v = fred[lane];
        #pragma unroll
        for (int o = 16; o; o >>= 1) v += __shfl_xor_sync(0xffffffffu, v, o);
        if (lane == 0) g_ssum = v;
    }
}

// ---------------------------------------------------------------------------
// Kernel 3: weighted mean/std over the compacted elite list. One block per t,
// lane = a, 16 warps stride the elite list.
// ---------------------------------------------------------------------------
__global__ void __launch_bounds__(512) reduce_kernel(const float* __restrict__ means,
                                                     const float* __restrict__ stds,
                                                     const float* __restrict__ noise,
                                                     float* __restrict__ out) {
    __shared__ float s1s[16][AA];
    __shared__ float s2s[16][AA];
    int t  = blockIdx.x;
    int a  = threadIdx.x & 31;
    int wg = threadIdx.x >> 5;  // 16 warps

    float mn = means[t * AA + a];
    float sd = stds[t * AA + a];
    const float* np = noise + (size_t)t * PP * AA;

    float s1 = 0.f, s2 = 0.f;
    for (int k = wg; k < KSEL; k += 16) {
        int   p = g_eidx[k];
        float w = g_ew[k];
        float x = fmaf(sd, np[(size_t)p * AA + a], mn);
        x = fminf(fmaxf(x, -1.f), 1.f);
        s1 = fmaf(w, x, s1);
        s2 = fmaf(w * x, x, s2);
    }
    s1s[wg][a] = s1; s2s[wg][a] = s2;
    __syncthreads();

    if (wg == 0) {
        float S1 = 0.f, S2 = 0.f;
        #pragma unroll
        for (int k = 0; k < 16; ++k) { S1 += s1s[k][a]; S2 += s2s[k][a]; }
        float ssum  = g_ssum;
        float denom = ssum + 1e-9f;
        float m   = S1 / denom;
        float var = (S2 - 2.f * m * S1 + m * m * ssum) / denom;
        var = fmaxf(var, 0.f);
        float st = sqrtf(var);
        st = fminf(fmaxf(st, 0.05f), 1.0f);
        out[t * AA + a]           = 0.1f * mn + 0.9f * m;
        out[TT * AA + t * AA + a] = st;
    }
}

extern "C" void kernel_launch(void* const* d_in, const int* in_sizes, int n_in,
                              void* d_out, int out_size) {
    const float* obs   = (const float*)d_in[0];  // [P, T, T]
    const float* means = (const float*)d_in[1];  // [T, 1, A]
    const float* stds  = (const float*)d_in[2];  // [T, 1, A]
    const float* noise = (const float*)d_in[3];  // [T, P, A]
    float* out = (float*)d_out;                  // [2, T, 1, A]

    dtw_kernel<<<PP / 8, 256>>>(obs);
    select_kernel<<<1, 1024>>>();
    reduce_kernel<<<TT, 512>>>(means, stds, noise, out);
}

// round 6
// speedup vs baseline: 2.2969x; 1.0026x over previous
#include <cuda_runtime.h>
#include <cuda_bf16.h>

#define PP   4096
#define TT   128
#define AA   32
#define KSEL 409
#define INF_F 1e30f
#define TEMP_F 0.5f

__device__ float    g_dists[PP];
__device__ int      g_eidx[KSEL];
__device__ float    g_ew[KSEL];
__device__ float    g_ssum;

// ---------------------------------------------------------------------------
// Kernel 1: DTW min-plus DP. One warp per p, 4 cols/lane.
// Row solve: D_j = S_j + prefmin_{k<=j}(e_k - S_k), S = prefix sums of costs.
// lp (= Dprev[4*lane-1]) is reconstructed as sum_ex + min_ex of the previous
// row (pd3 = S3 + g identity) -> no shfl at the head of the critical chain.
// Prefetch depth 4 covers DRAM latency (~577 cyc).
// ---------------------------------------------------------------------------
__device__ __forceinline__ void sum_scan(float4 c, int lane,
                                         float& S0, float& S1, float& S2, float& S3,
                                         float& sum_ex) {
    float s0 = c.x, s1 = s0 + c.y, s2 = s1 + c.z, s3 = s2 + c.w;
    float t = s3;
    #pragma unroll
    for (int d = 1; d < 32; d <<= 1) {
        float o = __shfl_up_sync(0xffffffffu, t, d);
        if (lane >= d) t += o;
    }
    sum_ex = t - s3;                 // = S3 of lane-1 (0 at lane 0)
    S0 = sum_ex + s0; S1 = sum_ex + s1; S2 = sum_ex + s2; S3 = t;
}

__global__ void __launch_bounds__(256) dtw_kernel(const float* __restrict__ obs) {
    int warp = (blockIdx.x * blockDim.x + threadIdx.x) >> 5;
    int lane = threadIdx.x & 31;
    const float4* row = (const float4*)obs + (size_t)warp * (TT * TT / 4) + lane;

    // prefetch depth 4
    float4 c0 = __ldcs(row);
    float4 c1 = __ldcs(row + 32);
    float4 c2 = __ldcs(row + 64);
    float4 c3 = __ldcs(row + 96);

    float S0, S1, S2, S3, sum_ex;
    sum_scan(c0, lane, S0, S1, S2, S3, sum_ex);

    float pd0 = INF_F, pd1 = INF_F, pd2 = INF_F, pd3 = INF_F;
    float lp = (lane == 0) ? 0.0f : INF_F;   // Dprev[4*lane-1] for row 0

    for (int i = 0; i < TT; ++i) {
        int nx = (i + 4 < TT) ? (i + 4) : (TT - 1);
        float4 c4 = __ldcs(row + nx * 32);

        float e0 = fminf(pd0, lp)  + c0.x;
        float e1 = fminf(pd1, pd0) + c0.y;
        float e2 = fminf(pd2, pd1) + c0.z;
        float e3 = fminf(pd3, pd2) + c0.w;

        // local inclusive prefix-min of m_j = e_j - S_j
        float l0 = e0 - S0;
        float l1 = fminf(l0, e1 - S1);
        float l2 = fminf(l1, e2 - S2);
        float l3 = fminf(l2, e3 - S3);

        // warp inclusive min-scan (unpredicated: shfl_up OOR returns own value)
        float g = l3;
        #pragma unroll
        for (int d = 1; d < 32; d <<= 1)
            g = fminf(g, __shfl_up_sync(0xffffffffu, g, d));

        float ex = __shfl_up_sync(0xffffffffu, g, 1);  // exclusive min carry
        if (lane == 0) ex = INF_F;

        pd0 = S0 + fminf(ex, l0);
        pd1 = S1 + fminf(ex, l1);
        pd2 = S2 + fminf(ex, l2);
        pd3 = S3 + fminf(ex, l3);

        // lp for next row: pd3[lane-1] = S3[lane-1] + g[lane-1] = sum_ex + ex
        // (lane 0: ex=INF -> lp=INF, the correct boundary for rows >= 1)
        lp = sum_ex + ex;

        // next row's sums (independent of the DP chain -> fills scan stalls)
        sum_scan(c1, lane, S0, S1, S2, S3, sum_ex);

        c0 = c1; c1 = c2; c2 = c3; c3 = c4;
    }
    if (lane == 31) g_dists[warp] = pd3;
}

// ---------------------------------------------------------------------------
// Kernel 2: single-block exact radix top-K + weights + elite compaction.
// ---------------------------------------------------------------------------
__global__ void __launch_bounds__(1024) select_kernel() {
    __shared__ unsigned hist[256];
    __shared__ unsigned wsum[32];
    __shared__ float    fred[32];
    __shared__ int      ired[32];
    __shared__ int      pofs[32];
    __shared__ float    s_min, s_Se;
    __shared__ unsigned s_prefix;
    __shared__ int      s_krem, s_cnt_lt;

    int tid = threadIdx.x, lane = tid & 31, wid = tid >> 5;

    float d[4]; unsigned u[4];
    float lmin = INF_F;
    #pragma unroll
    for (int e = 0; e < 4; ++e) {
        float x = g_dists[tid * 4 + e];
        d[e] = x;
        unsigned b = __float_as_uint(x);
        u[e] = b ^ ((b & 0x80000000u) ? 0xFFFFFFFFu : 0x80000000u);
        lmin = fminf(lmin, x);
    }
    if (tid == 0) { s_prefix = 0; s_krem = KSEL; s_cnt_lt = 0; }

    #pragma unroll
    for (int o = 16; o; o >>= 1) lmin = fminf(lmin, __shfl_xor_sync(0xffffffffu, lmin, o));
    if (lane == 0) fred[wid] = lmin;
    __syncthreads();
    if (wid == 0) {
        float v = fred[lane];
        #pragma unroll
        for (int o = 16; o; o >>= 1) v = fminf(v, __shfl_xor_sync(0xffffffffu, v, o));
        if (lane == 0) s_min = v;
    }
    __syncthreads();

    for (int shift = 24; shift >= 0; shift -= 8) {
        if (tid < 256) hist[tid] = 0;
        __syncthreads();
        unsigned pref  = s_prefix;
        int      krem  = s_krem;
        unsigned hmask = (shift == 24) ? 0u : (0xFFFFFFFFu << (shift + 8));
        #pragma unroll
        for (int e = 0; e < 4; ++e)
            if ((u[e] & hmask) == pref) atomicAdd(&hist[(u[e] >> shift) & 255], 1u);
        __syncthreads();
        unsigned v = 0, inc = 0;
        if (tid < 256) {
            v = hist[tid];
            inc = v;
            #pragma unroll
            for (int o = 1; o < 32; o <<= 1) {
                unsigned x = __shfl_up_sync(0xffffffffu, inc, o);
                if (lane >= o) inc += x;
            }
            if (lane == 31) wsum[wid] = inc;
        }
        __syncthreads();
        if (tid < 256) {
            unsigned off = 0;
            #pragma unroll
            for (int k = 0; k < 8; ++k) off += (k < wid) ? wsum[k] : 0u;
            unsigned cum  = off + inc;
            unsigned prev = cum - v;
            if (prev < (unsigned)krem && (unsigned)krem <= cum) {
                s_prefix = pref | ((unsigned)tid << shift);
                s_krem   = krem - (int)prev;
            }
        }
        __syncthreads();
    }
    unsigned tau = s_prefix;

    int clt = 0, tc = 0;
    #pragma unroll
    for (int e = 0; e < 4; ++e) { clt += (u[e] < tau); tc += (u[e] == tau); }
    atomicAdd(&s_cnt_lt, clt);

    int incl = tc;
    #pragma unroll
    for (int o = 1; o < 32; o <<= 1) { int v = __shfl_up_sync(0xffffffffu, incl, o); if (lane >= o) incl += v; }
    if (lane == 31) ired[wid] = incl;
    __syncthreads();
    if (wid == 0) {
        int v = ired[lane], s = v;
        #pragma unroll
        for (int o = 1; o < 32; o <<= 1) { int w2 = __shfl_up_sync(0xffffffffu, s, o); if (lane >= o) s += w2; }
        ired[lane] = s - v;
    }
    __syncthreads();

    int trank = ired[wid] + (incl - tc);
    int need  = KSEL - s_cnt_lt;
    float mind = s_min;

    bool  sel[4]; float ws[4]; float esum = 0.f; int nsel = 0;
    #pragma unroll
    for (int e = 0; e < 4; ++e) {
        bool s = (u[e] < tau);
        if (u[e] == tau) { s = (trank < need); trank++; }
        sel[e] = s;
        float w = s ? expf(TEMP_F * (mind - d[e])) : 0.f;
        ws[e] = w; esum += w; nsel += s;
    }

    float se = esum;
    #pragma unroll
    for (int o = 16; o; o >>= 1) se += __shfl_xor_sync(0xffffffffu, se, o);
    if (lane == 0) fred[wid] = se;
    __syncthreads();
    if (wid == 0) {
        float v = fred[lane];
        #pragma unroll
        for (int o = 16; o; o >>= 1) v += __shfl_xor_sync(0xffffffffu, v, o);
        if (lane == 0) s_Se = v;
    }
    __syncthreads();
    float Se = s_Se;

    int pincl = nsel;
    #pragma unroll
    for (int o = 1; o < 32; o <<= 1) { int v = __shfl_up_sync(0xffffffffu, pincl, o); if (lane >= o) pincl += v; }
    if (lane == 31) pofs[wid] = pincl;
    __syncthreads();
    if (wid == 0) {
        int v = pofs[lane], s = v;
        #pragma unroll
        for (int o = 1; o < 32; o <<= 1) { int w2 = __shfl_up_sync(0xffffffffu, s, o); if (lane >= o) s += w2; }
        pofs[lane] = s - v;
    }
    __syncthreads();
    int pos = pofs[wid] + (pincl - nsel);

    float ssl = 0.f;
    #pragma unroll
    for (int e = 0; e < 4; ++e) {
        if (sel[e]) {
            float sc = ws[e] / Se;
            g_eidx[pos] = tid * 4 + e;
            g_ew[pos]   = sc;
            pos++;
            ssl += sc;
        }
    }

    #pragma unroll
    for (int o = 16; o; o >>= 1) ssl += __shfl_xor_sync(0xffffffffu, ssl, o);
    if (lane == 0) fred[wid] = ssl;
    __syncthreads();
    if (wid == 0) {
        float v = fred[lane];
        #pragma unroll
        for (int o = 16; o; o >>= 1) v += __shfl_xor_sync(0xffffffffu, v, o);
        if (lane == 0) g_ssum = v;
    }
}

// ---------------------------------------------------------------------------
// Kernel 3: weighted mean/std over the compacted elite list. One block per t,
// lane = a, 16 warps stride the elite list.
// ---------------------------------------------------------------------------
__global__ void __launch_bounds__(512) reduce_kernel(const float* __restrict__ means,
                                                     const float* __restrict__ stds,
                                                     const float* __restrict__ noise,
                                                     float* __restrict__ out) {
    __shared__ float s1s[16][AA];
    __shared__ float s2s[16][AA];
    int t  = blockIdx.x;
    int a  = threadIdx.x & 31;
    int wg = threadIdx.x >> 5;

    float mn = means[t * AA + a];
    float sd = stds[t * AA + a];
    const float* np = noise + (size_t)t * PP * AA;

    float s1 = 0.f, s2 = 0.f;
    #pragma unroll 4
    for (int k = wg; k < KSEL; k += 16) {
        int   p = g_eidx[k];
        float w = g_ew[k];
        float x = fmaf(sd, __ldg(&np[(size_t)p * AA + a]), mn);
        x = fminf(fmaxf(x, -1.f), 1.f);
        s1 = fmaf(w, x, s1);
        s2 = fmaf(w * x, x, s2);
    }
    s1s[wg][a] = s1; s2s[wg][a] = s2;
    __syncthreads();

    if (wg == 0) {
        float S1 = 0.f, S2 = 0.f;
        #pragma unroll
        for (int k = 0; k < 16; ++k) { S1 += s1s[k][a]; S2 += s2s[k][a]; }
        float ssum  = g_ssum;
        float denom = ssum + 1e-9f;
        float m   = S1 / denom;
        float var = (S2 - 2.f * m * S1 + m * m * ssum) / denom;
        var = fmaxf(var, 0.f);
        float st = sqrtf(var);
        st = fminf(fmaxf(st, 0.05f), 1.0f);
        out[t * AA + a]           = 0.1f * mn + 0.9f * m;
        out[TT * AA + t * AA + a] = st;
    }
}

extern "C" void kernel_launch(void* const* d_in, const int* in_sizes, int n_in,
                              void* d_out, int out_size) {
    const float* obs   = (const float*)d_in[0];  // [P, T, T]
    const float* means = (const float*)d_in[1];  // [T, 1, A]
    const float* stds  = (const float*)d_in[2];  // [T, 1, A]
    const float* noise = (const float*)d_in[3];  // [T, P, A]
    float* out = (float*)d_out;                  // [2, T, 1, A]

    dtw_kernel<<<PP / 8, 256>>>(obs);
    select_kernel<<<1, 1024>>>();
    reduce_kernel<<<TT, 512>>>(means, stds, noise, out);
}